// round 12
// baseline (speedup 1.0000x reference)
#include <cuda_runtime.h>
#include <math.h>

#define NPROTO  10
#define NCLS    10
#define NPATCH  196
#define NFEAT   1960
#define BIMG    8192
#define NCHUNK  28       // half patch-rows: even -> pairs 0..3, odd -> pairs 4..6

typedef unsigned long long u64;

// scratch: [chunk][cls][img]
__device__ float g_scratch[NCHUNK * NCLS * BIMG];   // 9.2 MB

// ---- packed f32x2 helpers ---------------------------------------------------
__device__ __forceinline__ u64 pk2(float lo, float hi) {
    u64 r; asm("mov.b64 %0, {%1,%2};" : "=l"(r) : "f"(lo), "f"(hi)); return r;
}
__device__ __forceinline__ u64 fma2(u64 a, u64 b, u64 c) {
    u64 d; asm("fma.rn.f32x2 %0, %1, %2, %3;" : "=l"(d) : "l"(a), "l"(b), "l"(c)); return d;
}
__device__ __forceinline__ u64 mul2(u64 a, u64 b) {
    u64 d; asm("mul.rn.f32x2 %0, %1, %2;" : "=l"(d) : "l"(a), "l"(b)); return d;
}
__device__ __forceinline__ float2 up2(u64 a) {
    float2 f; asm("mov.b64 {%0,%1}, %2;" : "=f"(f.x), "=f"(f.y) : "l"(a)); return f;
}

// ---------------------------------------------------------------------------
// Stage 1: 896 CTAs x 64 (2 warps = 2 image groups, same half-row chunk).
// Warp covers 128 images (4/lane, image-packed f32x2: rp0=(i,i+32),
// rp1=(i+64,i+96)) x 4-or-3 patch pairs x 10 protos. Same inner loop as the
// 29.2us kernel; only the chunk split (and thus warps/SM: 6 -> 12) changed.
// __launch_bounds__(64, 6) caps regs at 170 so all 896 CTAs fit in ONE wave.
// ---------------------------------------------------------------------------
__global__ void __launch_bounds__(64, 6)
quanv_stage1(const float* __restrict__ x,
             const float* __restrict__ proto,
             const float* __restrict__ W)
{
    __shared__ __align__(16) u64 sWp[4 * 2 * NPROTO * NCLS];  // [jl][sub][p][c] dup
    __shared__ __align__(16) u64 sPc2[NPROTO * 4];
    __shared__ __align__(16) u64 sPs2[NPROTO * 4];

    const int tid   = threadIdx.x;
    const int chunk = blockIdx.x % NCHUNK;       // 0..27
    const int duo   = blockIdx.x / NCHUNK;       // 0..31
    const int row   = chunk >> 1;                // patch row 0..13
    const int half  = chunk & 1;
    const int j0    = half * 4;                  // first pair in row
    const int np    = half ? 3 : 4;              // pair count

    for (int i = tid; i < np * 200; i += 64) {
        const int jl  = i / 200,  rem = i - jl * 200;
        const int sub = rem / 100, r2 = rem - sub * 100;
        const int p   = r2 / 10,   c  = r2 - p * 10;
        const int patch = row * 14 + 2 * (j0 + jl) + sub;
        const float w = W[c * NFEAT + p * NPATCH + patch];
        sWp[i] = pk2(w, w);
    }
    if (tid < NPROTO * 4) {
        float s, c; __sincosf(0.5f * proto[tid], &s, &c);
        sPc2[tid] = pk2(c, c);
        sPs2[tid] = pk2(s, s);
    }
    __syncthreads();

    const int wid   = tid >> 5, lane = tid & 31;
    const int group = duo * 2 + wid;             // 0..63
    const int img0  = group * 128 + lane;

    const float* x0 = x + (size_t)(img0     ) * 784;
    const float* x1 = x + (size_t)(img0 + 32) * 784;
    const float* x2 = x + (size_t)(img0 + 64) * 784;
    const float* x3 = x + (size_t)(img0 + 96) * 784;

    u64 acc[2][NCLS];
    #pragma unroll
    for (int rp = 0; rp < 2; ++rp)
        #pragma unroll
        for (int c = 0; c < NCLS; ++c) acc[rp][c] = 0ULL;

    const int boff = row * 56;

    #pragma unroll 1
    for (int j = j0; j < j0 + np; ++j) {
        const int off = boff + 4 * j;            // 16B-aligned

        float4 vt0 = *reinterpret_cast<const float4*>(x0 + off);
        float4 vt1 = *reinterpret_cast<const float4*>(x1 + off);
        float4 vt2 = *reinterpret_cast<const float4*>(x2 + off);
        float4 vt3 = *reinterpret_cast<const float4*>(x3 + off);
        float4 vb0 = *reinterpret_cast<const float4*>(x0 + off + 28);
        float4 vb1 = *reinterpret_cast<const float4*>(x1 + off + 28);
        float4 vb2 = *reinterpret_cast<const float4*>(x2 + off + 28);
        float4 vb3 = *reinterpret_cast<const float4*>(x3 + off + 28);

        float ca[4][4], sa[4][4], cb[4][4], sb[4][4];     // [img][px]
        const float4 vt[4] = { vt0, vt1, vt2, vt3 };
        const float4 vb[4] = { vb0, vb1, vb2, vb3 };
        #pragma unroll
        for (int r = 0; r < 4; ++r) {
            __sincosf(0.5f * vt[r].x, &sa[r][0], &ca[r][0]);
            __sincosf(0.5f * vt[r].y, &sa[r][1], &ca[r][1]);
            __sincosf(0.5f * vb[r].x, &sa[r][2], &ca[r][2]);
            __sincosf(0.5f * vb[r].y, &sa[r][3], &ca[r][3]);
            __sincosf(0.5f * vt[r].z, &sb[r][0], &cb[r][0]);
            __sincosf(0.5f * vt[r].w, &sb[r][1], &cb[r][1]);
            __sincosf(0.5f * vb[r].z, &sb[r][2], &cb[r][2]);
            __sincosf(0.5f * vb[r].w, &sb[r][3], &cb[r][3]);
        }
        u64 cxa[2][4], sxa[2][4], cxb[2][4], sxb[2][4];
        #pragma unroll
        for (int k = 0; k < 4; ++k) {
            cxa[0][k] = pk2(ca[0][k], ca[1][k]);  sxa[0][k] = pk2(sa[0][k], sa[1][k]);
            cxa[1][k] = pk2(ca[2][k], ca[3][k]);  sxa[1][k] = pk2(sa[2][k], sa[3][k]);
            cxb[0][k] = pk2(cb[0][k], cb[1][k]);  sxb[0][k] = pk2(sb[0][k], sb[1][k]);
            cxb[1][k] = pk2(cb[2][k], cb[3][k]);  sxb[1][k] = pk2(sb[2][k], sb[3][k]);
        }

        const ulonglong2* wj = reinterpret_cast<const ulonglong2*>(&sWp[(j - j0) * 200]);

        #pragma unroll
        for (int p = 0; p < NPROTO; ++p) {
            const ulonglong2 cyA = *reinterpret_cast<const ulonglong2*>(&sPc2[p * 4]);
            const ulonglong2 cyB = *reinterpret_cast<const ulonglong2*>(&sPc2[p * 4 + 2]);
            const ulonglong2 syA = *reinterpret_cast<const ulonglong2*>(&sPs2[p * 4]);
            const ulonglong2 syB = *reinterpret_cast<const ulonglong2*>(&sPs2[p * 4 + 2]);

            u64 kqa[2], kqb[2];
            #pragma unroll
            for (int rp = 0; rp < 2; ++rp) {
                // cos((x-y)/2) = cos(x/2)cos(y/2) + sin(x/2)sin(y/2)
                u64 a0 = fma2(cxa[rp][0], cyA.x, mul2(sxa[rp][0], syA.x));
                u64 a1 = fma2(cxa[rp][1], cyA.y, mul2(sxa[rp][1], syA.y));
                u64 a2 = fma2(cxa[rp][2], cyB.x, mul2(sxa[rp][2], syB.x));
                u64 a3 = fma2(cxa[rp][3], cyB.y, mul2(sxa[rp][3], syB.y));
                kqa[rp] = mul2(mul2(a0, a1), mul2(a2, a3)) & 0x7FFFFFFF7FFFFFFFULL;

                u64 b0 = fma2(cxb[rp][0], cyA.x, mul2(sxb[rp][0], syA.x));
                u64 b1 = fma2(cxb[rp][1], cyA.y, mul2(sxb[rp][1], syA.y));
                u64 b2 = fma2(cxb[rp][2], cyB.x, mul2(sxb[rp][2], syB.x));
                u64 b3 = fma2(cxb[rp][3], cyB.y, mul2(sxb[rp][3], syB.y));
                kqb[rp] = mul2(mul2(b0, b1), mul2(b2, b3)) & 0x7FFFFFFF7FFFFFFFULL;
            }

            const ulonglong2* wpa = wj + p * 5;        // [jl][0][p][*]
            const ulonglong2* wpb = wj + 50 + p * 5;   // [jl][1][p][*]
            #pragma unroll
            for (int cc = 0; cc < 5; ++cc) {
                ulonglong2 wa = wpa[cc];
                ulonglong2 wb = wpb[cc];
                acc[0][cc*2  ] = fma2(kqa[0], wa.x, acc[0][cc*2  ]);
                acc[1][cc*2  ] = fma2(kqa[1], wa.x, acc[1][cc*2  ]);
                acc[0][cc*2+1] = fma2(kqa[0], wa.y, acc[0][cc*2+1]);
                acc[1][cc*2+1] = fma2(kqa[1], wa.y, acc[1][cc*2+1]);
                acc[0][cc*2  ] = fma2(kqb[0], wb.x, acc[0][cc*2  ]);
                acc[1][cc*2  ] = fma2(kqb[1], wb.x, acc[1][cc*2  ]);
                acc[0][cc*2+1] = fma2(kqb[0], wb.y, acc[0][cc*2+1]);
                acc[1][cc*2+1] = fma2(kqb[1], wb.y, acc[1][cc*2+1]);
            }
        }
    }

    // store [chunk][cls][img]: 4 coalesced STG.32 per class
    #pragma unroll
    for (int c = 0; c < NCLS; ++c) {
        float* base = g_scratch + ((size_t)chunk * NCLS + c) * BIMG + group * 128;
        float2 f0 = up2(acc[0][c]);
        float2 f1 = up2(acc[1][c]);
        base[lane     ] = f0.x;
        base[lane + 32] = f0.y;
        base[lane + 64] = f1.x;
        base[lane + 96] = f1.y;
    }
}

// ---------------------------------------------------------------------------
// Stage 2: 512 CTAs x 320. thread = (img 0..15, class 0..9, half 0..1);
// each sums 14 chunks (coalesced, independent). smem combine + log_softmax.
// 2x the parallelism of the previous 5.2us version.
// ---------------------------------------------------------------------------
__global__ void __launch_bounds__(320)
quanv_stage2(const float* __restrict__ bias, float* __restrict__ out)
{
    __shared__ float spart[2][16][11];   // [half][img][c], pad 11
    __shared__ float slse[16];

    const int tid   = threadIdx.x;
    const int img_l = tid & 15;
    const int rest  = tid >> 4;          // 0..19
    const int c     = rest % 10;
    const int half  = rest / 10;         // 0/1
    const int img   = blockIdx.x * 16 + img_l;

    float s = half ? 0.f : bias[c];
    #pragma unroll
    for (int k = 0; k < 14; ++k)
        s += g_scratch[((size_t)(half * 14 + k) * NCLS + c) * BIMG + img];
    spart[half][img_l][c] = s;
    __syncthreads();

    if (tid < 160) {
        const int im = tid & 15, c2 = tid >> 4;
        spart[0][im][c2] += spart[1][im][c2];
    }
    __syncthreads();

    if (tid < 16) {
        float m = spart[0][tid][0];
        #pragma unroll
        for (int k = 1; k < NCLS; ++k) m = fmaxf(m, spart[0][tid][k]);
        float ss = 0.f;
        #pragma unroll
        for (int k = 0; k < NCLS; ++k) ss += expf(spart[0][tid][k] - m);
        slse[tid] = m + logf(ss);
    }
    __syncthreads();

    if (tid < 160) {
        const int im = tid & 15, c2 = tid >> 4;
        out[(size_t)(blockIdx.x * 16 + im) * NCLS + c2] = spart[0][im][c2] - slse[im];
    }
}

// ---------------------------------------------------------------------------
extern "C" void kernel_launch(void* const* d_in, const int* in_sizes, int n_in,
                              void* d_out, int out_size)
{
    const float* x     = (const float*)d_in[0];  // (8192, 784)
    const float* proto = (const float*)d_in[1];  // (10, 4)
    const float* W     = (const float*)d_in[2];  // (10, 1960)
    const float* bias  = (const float*)d_in[3];  // (10,)
    float* out = (float*)d_out;                  // (8192, 10)

    quanv_stage1<<<32 * NCHUNK, 64>>>(x, proto, W);   // 896 CTAs, 12 warps/SM
    quanv_stage2<<<BIMG / 16, 320>>>(bias, out);      // 512 CTAs
}

// round 13
// speedup vs baseline: 1.3509x; 1.3509x over previous
#include <cuda_runtime.h>
#include <math.h>

#define NPROTO  10
#define NCLS    10
#define NPATCH  196
#define NFEAT   1960
#define BIMG    8192
#define NCHUNK  14       // chunk = one patch row (7 pairs)

typedef unsigned long long u64;

// scratch: [chunk][cls][img]
__device__ float g_scratch[NCHUNK * NCLS * BIMG];   // 4.6 MB

// ---- packed f32x2 helpers ---------------------------------------------------
__device__ __forceinline__ u64 pk2(float lo, float hi) {
    u64 r; asm("mov.b64 %0, {%1,%2};" : "=l"(r) : "f"(lo), "f"(hi)); return r;
}
__device__ __forceinline__ u64 fma2(u64 a, u64 b, u64 c) {
    u64 d; asm("fma.rn.f32x2 %0, %1, %2, %3;" : "=l"(d) : "l"(a), "l"(b), "l"(c)); return d;
}
__device__ __forceinline__ u64 mul2(u64 a, u64 b) {
    u64 d; asm("mul.rn.f32x2 %0, %1, %2;" : "=l"(d) : "l"(a), "l"(b)); return d;
}
__device__ __forceinline__ float2 up2(u64 a) {
    float2 f; asm("mov.b64 {%0,%1}, %2;" : "=f"(f.x), "=f"(f.y) : "l"(a)); return f;
}

// ---------------------------------------------------------------------------
// Stage 1 (R11 baseline, 29.2us): 448 CTAs x 64 (2 warps, same chunk, 2 image
// groups). Warp covers 128 images (4/lane, image-packed f32x2) x one patch
// ROW (7 pairs) x 10 protos. Patch pair shares x float4 loads; W dup-packed.
// CHANGE vs R11: proto-splat LDS (40 LDS.128 per pair, loop-invariant) hoisted
// into 40 u64 registers before the mainloop; j-loop back to unroll 1.
// ---------------------------------------------------------------------------
__global__ void __launch_bounds__(64)
quanv_stage1(const float* __restrict__ x,
             const float* __restrict__ proto,
             const float* __restrict__ W)
{
    __shared__ __align__(16) u64 sWp[7 * 2 * NPROTO * NCLS];  // [j][sub][p][c] dup
    __shared__ __align__(16) u64 sPc2[NPROTO * 4];
    __shared__ __align__(16) u64 sPs2[NPROTO * 4];

    const int tid   = threadIdx.x;
    const int chunk = blockIdx.x % NCHUNK;       // patch row 0..13
    const int duo   = blockIdx.x / NCHUNK;       // 0..31

    for (int i = tid; i < 1400; i += 64) {
        const int j   = i / 200,  rem = i - j * 200;
        const int sub = rem / 100, r2 = rem - sub * 100;
        const int p   = r2 / 10,   c  = r2 - p * 10;
        const float w = W[c * NFEAT + p * NPATCH + chunk * 14 + 2 * j + sub];
        sWp[i] = pk2(w, w);
    }
    if (tid < NPROTO * 4) {
        float s, c; __sincosf(0.5f * proto[tid], &s, &c);
        sPc2[tid] = pk2(c, c);
        sPs2[tid] = pk2(s, s);
    }
    __syncthreads();

    const int wid  = tid >> 5, lane = tid & 31;
    const int group = duo * 2 + wid;             // 0..63
    const int img0  = group * 128 + lane;

    const float* x0 = x + (size_t)(img0     ) * 784;
    const float* x1 = x + (size_t)(img0 + 32) * 784;
    const float* x2 = x + (size_t)(img0 + 64) * 784;
    const float* x3 = x + (size_t)(img0 + 96) * 784;

    // HOIST: proto splats into registers (loop-invariant across pairs)
    u64 cy[NPROTO][4], sy[NPROTO][4];
    #pragma unroll
    for (int p = 0; p < NPROTO; ++p) {
        ulonglong2 a = *reinterpret_cast<const ulonglong2*>(&sPc2[p * 4]);
        ulonglong2 b = *reinterpret_cast<const ulonglong2*>(&sPc2[p * 4 + 2]);
        cy[p][0] = a.x; cy[p][1] = a.y; cy[p][2] = b.x; cy[p][3] = b.y;
        ulonglong2 c2 = *reinterpret_cast<const ulonglong2*>(&sPs2[p * 4]);
        ulonglong2 d2 = *reinterpret_cast<const ulonglong2*>(&sPs2[p * 4 + 2]);
        sy[p][0] = c2.x; sy[p][1] = c2.y; sy[p][2] = d2.x; sy[p][3] = d2.y;
    }

    u64 acc[2][NCLS];
    #pragma unroll
    for (int rp = 0; rp < 2; ++rp)
        #pragma unroll
        for (int c = 0; c < NCLS; ++c) acc[rp][c] = 0ULL;

    const int boff = chunk * 56;                 // float offset of this patch row

    #pragma unroll 1
    for (int j = 0; j < 7; ++j) {
        const int off = boff + 4 * j;            // 16B-aligned

        // 2 LDG.128 per image fetch both patches of the pair
        float4 vt0 = *reinterpret_cast<const float4*>(x0 + off);
        float4 vt1 = *reinterpret_cast<const float4*>(x1 + off);
        float4 vt2 = *reinterpret_cast<const float4*>(x2 + off);
        float4 vt3 = *reinterpret_cast<const float4*>(x3 + off);
        float4 vb0 = *reinterpret_cast<const float4*>(x0 + off + 28);
        float4 vb1 = *reinterpret_cast<const float4*>(x1 + off + 28);
        float4 vb2 = *reinterpret_cast<const float4*>(x2 + off + 28);
        float4 vb3 = *reinterpret_cast<const float4*>(x3 + off + 28);

        // sincos: patch a px = (vt.x, vt.y, vb.x, vb.y); patch b = (vt.z, vt.w, vb.z, vb.w)
        float ca[4][4], sa[4][4], cb[4][4], sb[4][4];     // [img][px]
        const float4 vt[4] = { vt0, vt1, vt2, vt3 };
        const float4 vb[4] = { vb0, vb1, vb2, vb3 };
        #pragma unroll
        for (int r = 0; r < 4; ++r) {
            __sincosf(0.5f * vt[r].x, &sa[r][0], &ca[r][0]);
            __sincosf(0.5f * vt[r].y, &sa[r][1], &ca[r][1]);
            __sincosf(0.5f * vb[r].x, &sa[r][2], &ca[r][2]);
            __sincosf(0.5f * vb[r].y, &sa[r][3], &ca[r][3]);
            __sincosf(0.5f * vt[r].z, &sb[r][0], &cb[r][0]);
            __sincosf(0.5f * vt[r].w, &sb[r][1], &cb[r][1]);
            __sincosf(0.5f * vb[r].z, &sb[r][2], &cb[r][2]);
            __sincosf(0.5f * vb[r].w, &sb[r][3], &cb[r][3]);
        }
        // image-pack: rp0 = (img0, img0+32), rp1 = (img0+64, img0+96)
        u64 cxa[2][4], sxa[2][4], cxb[2][4], sxb[2][4];
        #pragma unroll
        for (int k = 0; k < 4; ++k) {
            cxa[0][k] = pk2(ca[0][k], ca[1][k]);  sxa[0][k] = pk2(sa[0][k], sa[1][k]);
            cxa[1][k] = pk2(ca[2][k], ca[3][k]);  sxa[1][k] = pk2(sa[2][k], sa[3][k]);
            cxb[0][k] = pk2(cb[0][k], cb[1][k]);  sxb[0][k] = pk2(sb[0][k], sb[1][k]);
            cxb[1][k] = pk2(cb[2][k], cb[3][k]);  sxb[1][k] = pk2(sb[2][k], sb[3][k]);
        }

        const ulonglong2* wj = reinterpret_cast<const ulonglong2*>(&sWp[j * 200]);

        #pragma unroll
        for (int p = 0; p < NPROTO; ++p) {
            u64 kqa[2], kqb[2];
            #pragma unroll
            for (int rp = 0; rp < 2; ++rp) {
                // cos((x-y)/2) = cos(x/2)cos(y/2) + sin(x/2)sin(y/2)
                u64 a0 = fma2(cxa[rp][0], cy[p][0], mul2(sxa[rp][0], sy[p][0]));
                u64 a1 = fma2(cxa[rp][1], cy[p][1], mul2(sxa[rp][1], sy[p][1]));
                u64 a2 = fma2(cxa[rp][2], cy[p][2], mul2(sxa[rp][2], sy[p][2]));
                u64 a3 = fma2(cxa[rp][3], cy[p][3], mul2(sxa[rp][3], sy[p][3]));
                kqa[rp] = mul2(mul2(a0, a1), mul2(a2, a3)) & 0x7FFFFFFF7FFFFFFFULL;

                u64 b0 = fma2(cxb[rp][0], cy[p][0], mul2(sxb[rp][0], sy[p][0]));
                u64 b1 = fma2(cxb[rp][1], cy[p][1], mul2(sxb[rp][1], sy[p][1]));
                u64 b2 = fma2(cxb[rp][2], cy[p][2], mul2(sxb[rp][2], sy[p][2]));
                u64 b3 = fma2(cxb[rp][3], cy[p][3], mul2(sxb[rp][3], sy[p][3]));
                kqb[rp] = mul2(mul2(b0, b1), mul2(b2, b3)) & 0x7FFFFFFF7FFFFFFFULL;
            }

            const ulonglong2* wpa = wj + p * 5;        // [j][0][p][*]
            const ulonglong2* wpb = wj + 50 + p * 5;   // [j][1][p][*]
            #pragma unroll
            for (int cc = 0; cc < 5; ++cc) {
                ulonglong2 wa = wpa[cc];
                ulonglong2 wb = wpb[cc];
                acc[0][cc*2  ] = fma2(kqa[0], wa.x, acc[0][cc*2  ]);
                acc[1][cc*2  ] = fma2(kqa[1], wa.x, acc[1][cc*2  ]);
                acc[0][cc*2+1] = fma2(kqa[0], wa.y, acc[0][cc*2+1]);
                acc[1][cc*2+1] = fma2(kqa[1], wa.y, acc[1][cc*2+1]);
                acc[0][cc*2  ] = fma2(kqb[0], wb.x, acc[0][cc*2  ]);
                acc[1][cc*2  ] = fma2(kqb[1], wb.x, acc[1][cc*2  ]);
                acc[0][cc*2+1] = fma2(kqb[0], wb.y, acc[0][cc*2+1]);
                acc[1][cc*2+1] = fma2(kqb[1], wb.y, acc[1][cc*2+1]);
            }
        }
    }

    // store [chunk][cls][img]: 4 coalesced STG.32 per class
    #pragma unroll
    for (int c = 0; c < NCLS; ++c) {
        float* base = g_scratch + ((size_t)chunk * NCLS + c) * BIMG + group * 128;
        float2 f0 = up2(acc[0][c]);
        float2 f1 = up2(acc[1][c]);
        base[lane     ] = f0.x;
        base[lane + 32] = f0.y;
        base[lane + 64] = f1.x;
        base[lane + 96] = f1.y;
    }
}

// ---------------------------------------------------------------------------
// Stage 2 (R11's exact form, 5.15us): 256 CTAs x 320, thread = (img, class),
// 14 coalesced independent chunk loads, smem exchange, log_softmax.
// ---------------------------------------------------------------------------
__global__ void __launch_bounds__(320)
quanv_stage2(const float* __restrict__ bias, float* __restrict__ out)
{
    __shared__ float slog[32 * 11];
    __shared__ float slse[32];

    const int tid   = threadIdx.x;
    const int img_l = tid & 31;
    const int c     = tid >> 5;          // 0..9
    const int img   = blockIdx.x * 32 + img_l;

    float s = bias[c];
    #pragma unroll
    for (int ch = 0; ch < NCHUNK; ++ch)
        s += g_scratch[((size_t)ch * NCLS + c) * BIMG + img];
    slog[img_l * 11 + c] = s;
    __syncthreads();

    if (tid < 32) {
        float m = slog[tid * 11];
        #pragma unroll
        for (int k = 1; k < NCLS; ++k) m = fmaxf(m, slog[tid * 11 + k]);
        float ss = 0.f;
        #pragma unroll
        for (int k = 0; k < NCLS; ++k) ss += expf(slog[tid * 11 + k] - m);
        slse[tid] = m + logf(ss);
    }
    __syncthreads();

    out[(size_t)img * NCLS + c] = slog[img_l * 11 + c] - slse[img_l];
}

// ---------------------------------------------------------------------------
extern "C" void kernel_launch(void* const* d_in, const int* in_sizes, int n_in,
                              void* d_out, int out_size)
{
    const float* x     = (const float*)d_in[0];  // (8192, 784)
    const float* proto = (const float*)d_in[1];  // (10, 4)
    const float* W     = (const float*)d_in[2];  // (10, 1960)
    const float* bias  = (const float*)d_in[3];  // (10,)
    float* out = (float*)d_out;                  // (8192, 10)

    quanv_stage1<<<32 * NCHUNK, 64>>>(x, proto, W);   // 448 CTAs
    quanv_stage2<<<BIMG / 32, 320>>>(bias, out);      // 256 CTAs
}